// round 1
// baseline (speedup 1.0000x reference)
#include <cuda_runtime.h>
#include <cuda_bf16.h>

// out[b,n] = sum_{m,j} W[b,n,m,j] * y[b,m,j] + fc_b[0]
// y[b,m,j] = sum_f x[b,m,f] * fc_w[j*32+f]
// Shapes: W [2,4096,4096,3] f32 (403 MB, streamed once -> HBM-bound),
//         x [2,4096,32], fc_w [1,96], fc_b [1], out [2,4096] f32.

#define NB 2
#define NN 4096
#define NJ 3
#define NF 32
#define ROW_LEN (NN * NJ)          // 12288 floats per W row / per y[b]
#define VROW (ROW_LEN / 4)         // 3072 float4
#define THREADS 256
#define V_PER_T (VROW / THREADS)   // 12 float4 per thread
#define ROWS_PER_BLOCK 8
#define BLOCKS_PER_B (NN / ROWS_PER_BLOCK)   // 512

__device__ __align__(16) float g_y[NB * ROW_LEN];

// Stage 1: fold fc_w into x -> y[b, m*3 + j]. Tiny (24576 outputs).
__global__ void gconv_stage1(const float* __restrict__ x,
                             const float* __restrict__ fcw) {
    int idx = blockIdx.x * blockDim.x + threadIdx.x;
    if (idx >= NB * NN * NJ) return;
    int j = idx % NJ;
    int m = (idx / NJ) % NN;
    int b = idx / (NJ * NN);
    const float* xr = x + (size_t)(b * NN + m) * NF;
    const float* wr = fcw + j * NF;
    float s = 0.f;
#pragma unroll
    for (int f = 0; f < NF; ++f) s += xr[f] * wr[f];
    g_y[idx] = s;
}

// Stage 2: per-block, load this batch's y slice into REGISTERS once
// (48 floats/thread), then stream ROWS_PER_BLOCK contiguous W rows from HBM
// with coalesced float4 loads and dot against the register-resident y.
__global__ void __launch_bounds__(THREADS)
gconv_stage2(const float* __restrict__ W,
             const float* __restrict__ fcb,
             float* __restrict__ out) {
    const int b  = blockIdx.x / BLOCKS_PER_B;
    const int n0 = (blockIdx.x % BLOCKS_PER_B) * ROWS_PER_BLOCK;
    const int t  = threadIdx.x;

    const float4* yv = reinterpret_cast<const float4*>(g_y + (size_t)b * ROW_LEN);
    float4 y[V_PER_T];
#pragma unroll
    for (int i = 0; i < V_PER_T; ++i) y[i] = yv[i * THREADS + t];

    __shared__ float red[THREADS / 32];
    const float bias = fcb[0];

    for (int r = 0; r < ROWS_PER_BLOCK; ++r) {
        const size_t row = (size_t)b * NN + (n0 + r);
        const float4* wv = reinterpret_cast<const float4*>(W + row * ROW_LEN);

        float acc = 0.f;
#pragma unroll
        for (int i = 0; i < V_PER_T; ++i) {
            float4 w = wv[i * THREADS + t];
            acc += w.x * y[i].x + w.y * y[i].y + w.z * y[i].z + w.w * y[i].w;
        }
        // warp reduce
#pragma unroll
        for (int o = 16; o > 0; o >>= 1)
            acc += __shfl_down_sync(0xffffffffu, acc, o);
        if ((t & 31) == 0) red[t >> 5] = acc;
        __syncthreads();
        if (t < 32) {
            float v = (t < THREADS / 32) ? red[t] : 0.f;
#pragma unroll
            for (int o = 4; o > 0; o >>= 1)
                v += __shfl_down_sync(0xffffffffu, v, o);
            if (t == 0) out[row] = v + bias;
        }
        __syncthreads();
    }
}

extern "C" void kernel_launch(void* const* d_in, const int* in_sizes, int n_in,
                              void* d_out, int out_size) {
    const float* W    = (const float*)d_in[0];   // [2,4096,4096,3]
    const float* x    = (const float*)d_in[1];   // [2,4096,32]
    const float* fc_w = (const float*)d_in[2];   // [1,96]
    const float* fc_b = (const float*)d_in[3];   // [1]
    float* out = (float*)d_out;                  // [2,4096]

    (void)in_sizes; (void)n_in; (void)out_size;

    gconv_stage1<<<(NB * NN * NJ + 255) / 256, 256>>>(x, fc_w);
    gconv_stage2<<<NB * BLOCKS_PER_B, THREADS>>>(W, fc_b, out);
}

// round 4
// speedup vs baseline: 1.0214x; 1.0214x over previous
#include <cuda_runtime.h>
#include <cuda_bf16.h>

// out[b,n] = sum_{m,j} W[b,n,m,j] * y[b,m,j] + fc_b[0]
// y[b,m,j] = sum_f x[b,m,f] * fc_w[j*32+f]
// W [2,4096,4096,3] f32 = 403 MB streamed once -> HBM-bound.

#define NB 2
#define NN 4096
#define NJ 3
#define NF 32
#define ROW_LEN (NN * NJ)          // 12288 floats per W row / per y[b]
#define VROW (ROW_LEN / 4)         // 3072 float4
#define THREADS 256
#define V_PER_T (VROW / THREADS)   // 12 float4 slices
#define RPB 8                      // rows per block
#define BLOCKS_PER_B (NN / RPB)    // 512

__device__ __align__(16) float g_y[NB * ROW_LEN];

// Stage 1: fold fc_w into x -> y[b, m*3 + j]. Tiny.
__global__ void gconv_stage1(const float* __restrict__ x,
                             const float* __restrict__ fcw) {
    int idx = blockIdx.x * blockDim.x + threadIdx.x;
    if (idx >= NB * NN * NJ) return;
    int j = idx % NJ;
    int m = (idx / NJ) % NN;
    int b = idx / (NJ * NN);
    const float* xr = x + (size_t)(b * NN + m) * NF;
    const float* wr = fcw + j * NF;
    float s = 0.f;
#pragma unroll
    for (int f = 0; f < NF; ++f) s += xr[f] * wr[f];
    g_y[idx] = s;
}

// Stage 2: outer loop over the 12 y-slices; per slice load y once (L2-resident)
// and accumulate 8 W rows concurrently -> 8 independent accumulators,
// 9 independent LDG.128 per iteration, ONE reduction/barrier phase per block.
__global__ void __launch_bounds__(THREADS)
gconv_stage2(const float* __restrict__ W,
             const float* __restrict__ fcb,
             float* __restrict__ out) {
    const int b  = blockIdx.x / BLOCKS_PER_B;
    const int n0 = (blockIdx.x % BLOCKS_PER_B) * RPB;
    const int t  = threadIdx.x;

    const float4* __restrict__ yv =
        reinterpret_cast<const float4*>(g_y + (size_t)b * ROW_LEN) + t;
    const float4* __restrict__ wv =
        reinterpret_cast<const float4*>(W + ((size_t)b * NN + n0) * ROW_LEN) + t;

    float acc[RPB];
#pragma unroll
    for (int r = 0; r < RPB; ++r) acc[r] = 0.f;

    for (int i = 0; i < V_PER_T; ++i) {
        const float4 yy = yv[i * THREADS];
        const float4* wp = wv + i * THREADS;
#pragma unroll
        for (int r = 0; r < RPB; ++r) {
            const float4 w = wp[(size_t)r * VROW];
            acc[r] += w.x * yy.x + w.y * yy.y + w.z * yy.z + w.w * yy.w;
        }
    }

    // Single reduction phase: warp-reduce each accumulator, cross-warp via
    // smem, threads 0..7 emit the 8 rows.
#pragma unroll
    for (int r = 0; r < RPB; ++r) {
#pragma unroll
        for (int o = 16; o > 0; o >>= 1)
            acc[r] += __shfl_down_sync(0xffffffffu, acc[r], o);
    }

    __shared__ float red[THREADS / 32][RPB];
    const int wid = t >> 5;
    if ((t & 31) == 0) {
#pragma unroll
        for (int r = 0; r < RPB; ++r) red[wid][r] = acc[r];
    }
    __syncthreads();

    if (t < RPB) {
        float v = 0.f;
#pragma unroll
        for (int w = 0; w < THREADS / 32; ++w) v += red[w][t];
        out[(size_t)b * NN + n0 + t] = v + fcb[0];
    }
}

extern "C" void kernel_launch(void* const* d_in, const int* in_sizes, int n_in,
                              void* d_out, int out_size) {
    const float* W    = (const float*)d_in[0];   // [2,4096,4096,3]
    const float* x    = (const float*)d_in[1];   // [2,4096,32]
    const float* fc_w = (const float*)d_in[2];   // [1,96]
    const float* fc_b = (const float*)d_in[3];   // [1]
    float* out = (float*)d_out;                  // [2,4096]

    (void)in_sizes; (void)n_in; (void)out_size;

    gconv_stage1<<<(NB * NN * NJ + 255) / 256, 256>>>(x, fc_w);
    gconv_stage2<<<NB * BLOCKS_PER_B, THREADS>>>(W, fc_b, out);
}

// round 6
// speedup vs baseline: 1.1519x; 1.1278x over previous
#include <cuda_runtime.h>
#include <cuda_bf16.h>

// out[b,n] = sum_{m,j} W[b,n,m,j] * y[b,m,j] + fc_b[0]
// y[b,m,j] = sum_f x[b,m,f] * fc_w[j*32+f]
// W [2,4096,4096,3] f32 = 403 MB streamed once -> HBM-bound.
// R6 == R5 resubmit: persistent CTAs + atomic work-stealing to kill
// intra-wave CTA spread/tail. (R5 bench was an infra failure, not a verdict.)

#define NB 2
#define NN 4096
#define NJ 3
#define NF 32
#define ROW_LEN (NN * NJ)          // 12288 floats per W row / per y[b]
#define VROW (ROW_LEN / 4)         // 3072 float4
#define THREADS 256
#define NWARP (THREADS / 32)
#define V_PER_T (VROW / THREADS)   // 12 float4 slices
#define RPB 4                      // rows per tile
#define TILES_PER_B (NN / RPB)     // 1024
#define NTILES (NB * TILES_PER_B)  // 2048
#define GRID2 (148 * 4)            // persistent CTAs

__device__ __align__(16) float g_y[NB * ROW_LEN];
__device__ unsigned g_ctr;

// Stage 1: fold fc_w into x -> y[b, m*3 + j]; also reset the work counter.
__global__ void gconv_stage1(const float* __restrict__ x,
                             const float* __restrict__ fcw) {
    int idx = blockIdx.x * blockDim.x + threadIdx.x;
    if (idx == 0) g_ctr = 0u;
    if (idx >= NB * NN * NJ) return;
    int j = idx % NJ;
    int m = (idx / NJ) % NN;
    int b = idx / (NJ * NN);
    const float* xr = x + (size_t)(b * NN + m) * NF;
    const float* wr = fcw + j * NF;
    float s = 0.f;
#pragma unroll
    for (int f = 0; f < NF; ++f) s += xr[f] * wr[f];
    g_y[idx] = s;
}

// Stage 2: persistent CTAs pop 4-row tiles off g_ctr. Per tile: loop the 12
// y-slices (L1-resident re-reads), 4 concurrent W-row accumulators streamed
// with __ldcs (read-once, evict-first), one barrier per tile via
// parity-indexed smem reduction buffers.
__global__ void __launch_bounds__(THREADS)
gconv_stage2(const float* __restrict__ W,
             const float* __restrict__ fcb,
             float* __restrict__ out) {
    const int t   = threadIdx.x;
    const int wid = t >> 5;
    const float bias = fcb[0];

    __shared__ float red[2][NWARP][RPB];
    __shared__ unsigned s_tile;

    int par = 0;
    for (;;) {
        if (t == 0) s_tile = atomicAdd(&g_ctr, 1u);
        __syncthreads();                      // publishes s_tile
        const unsigned tile = s_tile;
        if (tile >= NTILES) break;

        const int b  = tile / TILES_PER_B;
        const int n0 = (tile % TILES_PER_B) * RPB;

        const float4* __restrict__ yv =
            reinterpret_cast<const float4*>(g_y + (size_t)b * ROW_LEN) + t;
        const float4* __restrict__ wv =
            reinterpret_cast<const float4*>(W + ((size_t)b * NN + n0) * ROW_LEN) + t;

        float acc[RPB];
#pragma unroll
        for (int r = 0; r < RPB; ++r) acc[r] = 0.f;

#pragma unroll 2
        for (int i = 0; i < V_PER_T; ++i) {
            const float4 yy = yv[i * THREADS];
            const float4* wp = wv + i * THREADS;
#pragma unroll
            for (int r = 0; r < RPB; ++r) {
                const float4 w = __ldcs(wp + (size_t)r * VROW);
                acc[r] += w.x * yy.x + w.y * yy.y + w.z * yy.z + w.w * yy.w;
            }
        }

        // warp-reduce each accumulator
#pragma unroll
        for (int r = 0; r < RPB; ++r) {
#pragma unroll
            for (int o = 16; o > 0; o >>= 1)
                acc[r] += __shfl_down_sync(0xffffffffu, acc[r], o);
        }
        if ((t & 31) == 0) {
#pragma unroll
            for (int r = 0; r < RPB; ++r) red[par][wid][r] = acc[r];
        }
        __syncthreads();                      // red[par] ready
        if (t < RPB) {
            float v = 0.f;
#pragma unroll
            for (int w = 0; w < NWARP; ++w) v += red[par][w][t];
            out[(size_t)b * NN + n0 + t] = v + bias;
        }
        par ^= 1;                             // next tile writes the other buffer
    }
}

extern "C" void kernel_launch(void* const* d_in, const int* in_sizes, int n_in,
                              void* d_out, int out_size) {
    const float* W    = (const float*)d_in[0];   // [2,4096,4096,3]
    const float* x    = (const float*)d_in[1];   // [2,4096,32]
    const float* fc_w = (const float*)d_in[2];   // [1,96]
    const float* fc_b = (const float*)d_in[3];   // [1]
    float* out = (float*)d_out;                  // [2,4096]

    (void)in_sizes; (void)n_in; (void)out_size;

    gconv_stage1<<<(NB * NN * NJ + 255) / 256, 256>>>(x, fc_w);
    gconv_stage2<<<GRID2, THREADS>>>(W, fc_b, out);
}